// round 8
// baseline (speedup 1.0000x reference)
#include <cuda_runtime.h>
#include <math.h>
#include <stdint.h>

#define BATCH 8
#define TOTAL 21824
#define DETS  100
#define IMGF  1024.0f
#define STH   0.2f
#define NMST  0.6f
#define MAXB  128    // bucket capacity per (batch,class); mean ~41, 13-sigma safe
#define BINN  4096   // quantization bins
#define BCAP  512    // boundary-bin capacity (expected ~16)
#define OCAP  1024   // out contention capacity (expected ~110)
#define SCAP  4096   // compact survivor capacity per batch (expected ~2000)

// ---------------- scratch ----------------
__device__ unsigned long long d_keys[BATCH * TOTAL];
__device__ unsigned long long d_bucket[BATCH * 80 * MAXB];
__device__ int                d_ccnt[BATCH * 80];
__device__ unsigned long long d_sur[BATCH * SCAP];
__device__ int                d_surtot[BATCH];
__device__ int                d_sel_done[BATCH];
__device__ int                d_nms_done[BATCH];

__device__ __forceinline__ float sigf(float x) { return 1.0f / (1.0f + expf(-x)); }

__device__ __forceinline__ float key_score_hi(unsigned h) {
    unsigned uo = ~h;
    unsigned bits = (uo & 0x80000000u) ? (uo ^ 0x80000000u) : (~uo);
    return __uint_as_float(bits);
}
__device__ __forceinline__ float key_score(unsigned long long key) {
    return key_score_hi((unsigned)(key >> 32));
}
// monotone: higher score -> higher bin; masked (-1) -> bin 0
__device__ __forceinline__ int qbin(unsigned h) {
    float s = key_score_hi(h);
    return (s > 0.0f) ? min(BINN - 1, (int)(s * (float)BINN)) : 0;
}

__device__ __forceinline__ void bucket_push(int b, unsigned long long key) {
    int c = (int)(key & 127ULL);
    int pos = atomicAdd(&d_ccnt[b * 80 + c], 1);
    if (pos < MAXB) d_bucket[(size_t)(b * 80 + c) * MAXB + pos] = key;
}

// ---------------- K1: staged coalesced score + argmax -> 64-bit key ----------------
// key = (~orderable(score))<<32 | idx<<7 | label : ascending == (score desc, idx asc);
// keys globally distinct; matches jax.lax.top_k stable tie order.
__global__ __launch_bounds__(512) void k_score(const float* __restrict__ logits,
                                               const float* __restrict__ ctr) {
    __shared__ float4 s4[128 * 20];  // 40 KB
    int tid = threadIdx.x;
    if (blockIdx.x == 0) {
        for (int i = tid; i < BATCH * 80; i += 512) d_ccnt[i] = 0;
        if (tid < BATCH) {
            d_surtot[tid] = 0;
            d_sel_done[tid] = 0;
            d_nms_done[tid] = 0;
        }
    }
    const float4* g = reinterpret_cast<const float4*>(logits) + (size_t)blockIdx.x * (128 * 20);
#pragma unroll
    for (int i = 0; i < 5; i++) s4[i * 512 + tid] = __ldcs(&g[i * 512 + tid]);
    __syncthreads();

    int la = tid >> 2;   // local anchor 0..127
    int q  = tid & 3;    // quarter: cols 20q..20q+19
    const float4* rowq = s4 + la * 20 + q * 5;
    float best = -1e30f;
    int bi = 0;
#pragma unroll
    for (int i = 0; i < 5; i++) {  // strict > keeps first-max within lane
        float4 v = rowq[i];
        int cb = q * 20 + i * 4;
        if (v.x > best) { best = v.x; bi = cb + 0; }
        if (v.y > best) { best = v.y; bi = cb + 1; }
        if (v.z > best) { best = v.z; bi = cb + 2; }
        if (v.w > best) { best = v.w; bi = cb + 3; }
    }
#pragma unroll
    for (int o = 2; o >= 1; o >>= 1) {  // tie -> lower column (= first occurrence)
        float ov = __shfl_down_sync(0xFFFFFFFFu, best, o);
        int   oc = __shfl_down_sync(0xFFFFFFFFu, bi, o);
        if (ov > best || (ov == best && oc < bi)) { best = ov; bi = oc; }
    }
    if (q == 0) {
        int ga = blockIdx.x * 128 + la;   // BATCH*TOTAL % 128 == 0
        float s = sqrtf(sigf(best) * sigf(ctr[ga]));
        float sm = (s > STH) ? s : -1.0f;
        unsigned u = __float_as_uint(sm);
        u ^= (u & 0x80000000u) ? 0xFFFFFFFFu : 0x80000000u;
        int i_loc = ga % TOTAL;
        d_keys[ga] = ((unsigned long long)(~u) << 32) |
                     ((unsigned)(i_loc << 7) | (unsigned)bi);
    }
}

// ======================= K2: fused select + NMS + out =======================
// grid: [0,40) select (batch,level) | [40,80) nms (batch, 16-class group) |
//       [80,88) out (batch). All 88 blocks co-resident; stage handoff via
//       done-counters + threadfence; cross-block reads use __ldcg (L2-coherent).
#define NMS_STRIDE 4352   // per-warp smem: kb 1024 | bx 2048 | ar 512 | sv 512 | rm 128 (+pad)
#define REST_SMEM  (16 * NMS_STRIDE)   // 69632 B (max over the three roles)

__global__ __launch_bounds__(512, 1) void k_rest(const float* __restrict__ reg,
                                                 const float* __restrict__ anchors,
                                                 float* __restrict__ out) {
    extern __shared__ unsigned char sm[];
    int bid = blockIdx.x, tid = threadIdx.x, lane = tid & 31, wid = tid >> 5;

    // ---------------- role: SELECT ----------------
    if (bid < 40) {
        const int LOFF[5] = {0, 16384, 20480, 21504, 21760};
        const int LN[5]   = {16384, 4096, 1024, 256, 64};
        const int LK[5]   = {1000, 1000, 1000, 256, 64};
        int b = bid / 5, lvl = bid % 5;
        int off = LOFF[lvl], n = LN[lvl], k = LK[lvl];
        const unsigned long long* kp = d_keys + b * TOTAL + off;

        if (k >= n) {  // levels 3,4: everything selected
            for (int i = tid; i < n; i += 512) bucket_push(b, kp[i]);
            __syncthreads();
            __threadfence();
            if (tid == 0) atomicAdd(&d_sel_done[b], 1);
            return;
        }

        unsigned* hist = (unsigned*)sm;                         // 16 KB
        unsigned long long* binkeys = (unsigned long long*)(sm + BINN * 4);  // 4 KB
        __shared__ int warpsum[16];
        __shared__ unsigned long long sh_pivot;
        __shared__ int sh_Q, sh_kneed, sh_bc;

        for (int i = tid; i < BINN; i += 512) hist[i] = 0;
        if (tid == 0) sh_bc = 0;
        __syncthreads();

        // sweep 1: histogram (n is a multiple of 512)
        for (int i = tid; i < n; i += 512) {
            int q = qbin((unsigned)(kp[i] >> 32));
            unsigned peers = __match_any_sync(0xFFFFFFFFu, q);
            if (lane == __ffs(peers) - 1) atomicAdd(&hist[q], __popc(peers));
        }
        __syncthreads();

        // descending-bin cumulative scan (8 bins/thread): boundary bin Q, kneed
        {
            int vv[8], mysum = 0;
#pragma unroll
            for (int j = 0; j < 8; j++) { vv[j] = hist[BINN - 1 - (tid * 8 + j)]; mysum += vv[j]; }
            int inc = mysum;
#pragma unroll
            for (int o = 1; o < 32; o <<= 1) { int t2 = __shfl_up_sync(0xFFFFFFFFu, inc, o); if (lane >= o) inc += t2; }
            if (lane == 31) warpsum[wid] = inc;
            __syncthreads();
            if (tid < 16) {
                int w = warpsum[tid], s = w;
#pragma unroll
                for (int o = 1; o < 16; o <<= 1) { int t2 = __shfl_up_sync(0xFFFFu, s, o); if (tid >= o) s += t2; }
                warpsum[tid] = s - w;
            }
            __syncthreads();
            int c = warpsum[wid] + inc - mysum;
#pragma unroll
            for (int j = 0; j < 8; j++) {
                if (c < k && c + vv[j] >= k) {
                    sh_Q = BINN - 1 - (tid * 8 + j);
                    sh_kneed = k - c;
                }
                c += vv[j];
            }
        }
        __syncthreads();
        int Q = sh_Q, kneed = sh_kneed;

        // sweep 2: gather boundary bin
        for (int i = tid; i < n; i += 512) {
            unsigned long long key = kp[i];
            if (qbin((unsigned)(key >> 32)) == Q) {
                int p = atomicAdd(&sh_bc, 1);
                if (p < BCAP) binkeys[p] = key;
            }
        }
        __syncthreads();
        int C = min(sh_bc, BCAP);

        // exact rank: pivot = (kneed-1)-th smallest key in the bin (keys distinct)
        for (int t = tid; t < C; t += 512) {
            unsigned long long mk = binkeys[t];
            int r = 0;
            for (int j2 = 0; j2 < C; j2++) r += (binkeys[j2] < mk);
            if (r == kneed - 1) sh_pivot = mk;
        }
        __syncthreads();
        unsigned long long pivot = sh_pivot;

        // sweep 3: scatter exactly k keys into class buckets
        for (int i = tid; i < n; i += 512) {
            unsigned long long key = kp[i];
            int q = qbin((unsigned)(key >> 32));
            if (q > Q || (q == Q && key <= pivot)) bucket_push(b, key);
        }
        __syncthreads();
        __threadfence();
        if (tid == 0) atomicAdd(&d_sel_done[b], 1);
        return;
    }

    // ---------------- role: NMS (16 classes, one warp each) ----------------
    if (bid < 80) {
        int t = bid - 40;
        int b = t / 5;
        int c = (t % 5) * 16 + wid;
        int bc = b * 80 + c;

        if (tid == 0) {
            while (atomicAdd(&d_sel_done[b], 0) < 5) __nanosleep(64);
        }
        __syncthreads();
        __threadfence();

        unsigned char* base = sm + wid * NMS_STRIDE;
        unsigned long long* kb = (unsigned long long*)base;
        float4* bxs = (float4*)(base + 1024);
        float*  ar  = (float*)(base + 3072);
        float*  sv  = (float*)(base + 3584);
        unsigned char* rm = base + 4096;

        int cnt = min(__ldcg(&d_ccnt[bc]), MAXB);
        int wcnt = 0;
        if (cnt > 0) {
            for (int i = lane; i < cnt; i += 32)
                kb[i] = __ldcg(&d_bucket[(size_t)bc * MAXB + i]);
            __syncwarp();

            // warp bitonic sort ascending (== score desc, idx asc)
            int m = 2; while (m < cnt) m <<= 1;
            for (int i = lane; i < m; i += 32) if (i >= cnt) kb[i] = ~0ULL;
            __syncwarp();
            for (int kk = 2; kk <= m; kk <<= 1)
                for (int jj = kk >> 1; jj > 0; jj >>= 1) {
                    for (int cc = lane; cc < (m >> 1); cc += 32) {
                        int i1 = ((cc & ~(jj - 1)) << 1) | (cc & (jj - 1));
                        int l1 = i1 | jj;
                        bool up = ((i1 & kk) == 0);
                        unsigned long long a2 = kb[i1], d2 = kb[l1];
                        if ((a2 > d2) == up) { kb[i1] = d2; kb[l1] = a2; }
                    }
                    __syncwarp();
                }

            // decode
            for (int i = lane; i < cnt; i += 32) {
                unsigned long long key = kb[i];
                int idx = (int)((key >> 7) & 0x7FFFULL);
                sv[i] = key_score(key);
                rm[i] = 0;
                float4 an = reinterpret_cast<const float4*>(anchors)[idx];
                float cx = (an.x + an.z) * 0.5f, cy = (an.y + an.w) * 0.5f;
                float4 r = reinterpret_cast<const float4*>(reg)[(size_t)b * TOTAL + idx];
                float x1 = fminf(fmaxf(cx - r.x, 0.0f), IMGF);
                float y1 = fminf(fmaxf(cy - r.y, 0.0f), IMGF);
                float x2 = fminf(fmaxf(cx + r.z, 0.0f), IMGF);
                float y2 = fminf(fmaxf(cy + r.w, 0.0f), IMGF);
                bxs[i] = make_float4(x1, y1, x2, y2);
                ar[i] = fmaxf(x2 - x1, 0.0f) * fmaxf(y2 - y1, 0.0f);
            }
            __syncwarp();

            // greedy NMS (masked sort last; suppressed never suppress)
            for (int i = 0; i < cnt; i++) {
                if (sv[i] <= STH) break;
                if (rm[i]) continue;
                float4 bi = bxs[i];
                float ai = ar[i];
                for (int j = i + 1 + lane; j < cnt; j += 32) {
                    float4 bj = bxs[j];
                    float iw = fmaxf(fminf(bi.z, bj.z) - fmaxf(bi.x, bj.x), 0.0f);
                    float ih = fmaxf(fminf(bi.w, bj.w) - fmaxf(bi.y, bj.y), 0.0f);
                    float inter = iw * ih;
                    float iou = inter / fmaxf(ai + ar[j] - inter, 1e-9f);
                    if (iou > NMST) rm[j] = 1;
                }
                __syncwarp();
            }

            // append survivors (per-class cap DETS) to compact per-batch list
            for (int base2 = 0; base2 < cnt; base2 += 32) {
                int i = base2 + lane;
                bool acc = (i < cnt) && (sv[i] > STH) && !rm[i];
                unsigned bal = __ballot_sync(0xFFFFFFFFu, acc);
                int nb = __popc(bal);
                int nTake = min(nb, max(0, DETS - wcnt));
                int pos = 0;
                if (lane == 0 && nTake > 0) pos = atomicAdd(&d_surtot[b], nTake);
                pos = __shfl_sync(0xFFFFFFFFu, pos, 0);
                int rk = __popc(bal & ((1u << lane) - 1));
                if (acc && rk < nTake) d_sur[(size_t)b * SCAP + pos + rk] = kb[i];
                wcnt += nb;
            }
        }
        __syncthreads();
        __threadfence();
        if (tid == 0) atomicAdd(&d_nms_done[b], 1);
        return;
    }

    // ---------------- role: OUT (per-batch top-100) ----------------
    {
        int b = bid - 80;
        if (tid == 0) {
            while (atomicAdd(&d_nms_done[b], 0) < 5) __nanosleep(64);
        }
        __syncthreads();
        __threadfence();

        unsigned long long* skey = (unsigned long long*)sm;            // 32 KB
        unsigned* hist = (unsigned*)(sm + SCAP * 8);                   // 16 KB
        unsigned long long* cont = (unsigned long long*)(sm + SCAP * 8 + BINN * 4);  // 8 KB
        __shared__ unsigned long long win[DETS];
        __shared__ int warpsum[16];
        __shared__ int sh_cc, sh_Q;

        int S = min(__ldcg(&d_surtot[b]), SCAP);
        int ns = min(DETS, S);

        for (int i = tid; i < BINN; i += 512) hist[i] = 0;
        if (tid == 0) { sh_cc = 0; sh_Q = 0; }
        __syncthreads();

        for (int i = tid; i < S; i += 512) {
            unsigned long long key = __ldcg(&d_sur[(size_t)b * SCAP + i]);
            skey[i] = key;
            atomicAdd(&hist[qbin((unsigned)(key >> 32))], 1u);
        }
        __syncthreads();

        if (ns > 0) {
            // descending-bin scan: first bin where cum >= ns
            int vv[8], mysum = 0;
#pragma unroll
            for (int j = 0; j < 8; j++) { vv[j] = hist[BINN - 1 - (tid * 8 + j)]; mysum += vv[j]; }
            int inc = mysum;
#pragma unroll
            for (int o = 1; o < 32; o <<= 1) { int t2 = __shfl_up_sync(0xFFFFFFFFu, inc, o); if (lane >= o) inc += t2; }
            if (lane == 31) warpsum[wid] = inc;
            __syncthreads();
            if (tid < 16) {
                int w = warpsum[tid], s = w;
#pragma unroll
                for (int o = 1; o < 16; o <<= 1) { int t2 = __shfl_up_sync(0xFFFFu, s, o); if (tid >= o) s += t2; }
                warpsum[tid] = s - w;
            }
            __syncthreads();
            int c = warpsum[wid] + inc - mysum;
#pragma unroll
            for (int j = 0; j < 8; j++) {
                if (c < ns && c + vv[j] >= ns) sh_Q = BINN - 1 - (tid * 8 + j);
                c += vv[j];
            }
            __syncthreads();
            int Q = sh_Q;

            // contention = all bins >= Q (superset of the top-ns)
            for (int i = tid; i < S; i += 512) {
                unsigned long long key = skey[i];
                if (qbin((unsigned)(key >> 32)) >= Q) {
                    int p = atomicAdd(&sh_cc, 1);
                    if (p < OCAP) cont[p] = key;
                }
            }
            __syncthreads();
            int C = min(sh_cc, OCAP);

            // exact rank within contention == global rank for r < ns
            for (int t = tid; t < C; t += 512) {
                unsigned long long mk = cont[t];
                int r = 0;
                for (int q2 = 0; q2 < C; q2++) r += (cont[q2] < mk);
                if (r < ns) win[r] = mk;
            }
        }
        __syncthreads();

        // decode + write
        for (int t = tid; t < DETS; t += 512) {
            float* ob = out + ((size_t)b * DETS + t) * 4;
            if (t >= ns) {
                ob[0] = 0.0f; ob[1] = 0.0f; ob[2] = 0.0f; ob[3] = 0.0f;
                out[BATCH * DETS * 4 + b * DETS + t] = 0.0f;
                out[BATCH * DETS * 5 + b * DETS + t] = -1.0f;
            } else {
                unsigned long long key = win[t];
                int idx = (int)((key >> 7) & 0x7FFFULL);
                float4 an = reinterpret_cast<const float4*>(anchors)[idx];
                float cx = (an.x + an.z) * 0.5f, cy = (an.y + an.w) * 0.5f;
                float4 r = reinterpret_cast<const float4*>(reg)[(size_t)b * TOTAL + idx];
                float x1 = fminf(fmaxf(cx - r.x, 0.0f), IMGF);
                float y1 = fminf(fmaxf(cy - r.y, 0.0f), IMGF);
                float x2 = fminf(fmaxf(cx + r.z, 0.0f), IMGF);
                float y2 = fminf(fmaxf(cy + r.w, 0.0f), IMGF);
                ob[0] = x1; ob[1] = y1; ob[2] = x2; ob[3] = y2;
                out[BATCH * DETS * 4 + b * DETS + t] = key_score(key);
                out[BATCH * DETS * 5 + b * DETS + t] = (float)(key & 127ULL);
            }
        }
    }
}

// ---------------- launch ----------------
extern "C" void kernel_launch(void* const* d_in, const int* in_sizes, int n_in,
                              void* d_out, int out_size) {
    const float* logits  = (const float*)d_in[0];  // (8, 21824, 80)
    const float* reg     = (const float*)d_in[1];  // (8, 21824, 4)
    const float* ctr     = (const float*)d_in[2];  // (8, 21824, 1)
    const float* anchors = (const float*)d_in[3];  // (21824, 4)
    float* out = (float*)d_out;

    cudaFuncSetAttribute(k_rest, cudaFuncAttributeMaxDynamicSharedMemorySize, REST_SMEM);

    k_score<<<(BATCH * TOTAL) / 128, 512>>>(logits, ctr);
    k_rest<<<88, 512, REST_SMEM>>>(reg, anchors, out);
}